// round 9
// baseline (speedup 1.0000x reference)
#include <cuda_runtime.h>
#include <math.h>
#include <stdint.h>

// FootAndBall ball-detection post-process — SINGLE kernel, vectorized.
//  in : [16, 2, 540, 960] fp32 logits
//  out: [16, 100, 5] fp32 (x1,y1,x2,y2,score), score desc (idx asc on ties).
//
//  Phase 1 (all 576 blocks): d = x1-x0 (NMS on d == NMS on softmax prob,
//    monotone). float4 register-streaming 3x3 NMS: lane owns 4 columns,
//    warp covers 128 cols (120 outputs), rows streamed with a rolling
//    vertical max; only 2 shuffles per 4 pixels, no ballots. Rare candidates
//    (~0.7%) append to a block smem queue + smem histogram. Block-local
//    top-100 cut filters the queue before the global flush (~80/block kept).
//    Global top-100 ⊆ union of block-local top-100s; queue overflow falls
//    back to direct unfiltered global append (superset -> still correct).
//  Phase 2 (last-arriving block per batch): per-batch histogram of the ~3.6k
//    surviving candidates (L2-hot), cut, collect, exact (p desc, idx asc)
//    rank, box write, state reset for the next graph replay.
//  __device__ globals start zero-initialized; Phase 2 restores zeros.

#define BB   16
#define HH   540
#define WW   960
#define HWSZ (HH * WW)
#define KK   100

#define NT    256                 // threads per block (8 warps)
#define RPB   15                  // rows per block; 540 = 36 * 15
#define NBY   36                  // blocks per batch
#define QC    2048                // block smem queue entries (16 KB)
#define CAP   2048                // selector survivor capacity (overlay)
#define SEGC  16384               // global per-(b,by) capacity (worst 14400)
#define HB    4096                // histogram bins (top 12 flipped bits)

__device__ int    g_cnt [BB][NBY];
__device__ int    g_done[BB];
__device__ float2 g_cand[BB][NBY][SEGC];

// ---------------------------------------------------------------------------
// Exact softmax channel-1 prob from d = fl(x1-x0). Matches jax.nn.softmax:
// one exp arg is exactly 0 and fl(x0-x1) == -d exactly. (rel_err ~1e-12.)
// ---------------------------------------------------------------------------
__device__ __forceinline__ float prob_from_d(float d) {
#ifdef __FAST_MATH__
    double dd = (double)d;
    double p = (d >= 0.0f) ? (1.0 / (exp(-dd) + 1.0))
                           : (exp(dd) / (exp(dd) + 1.0));
    return (float)p;
#else
    if (d >= 0.0f) { float e0 = expf(-d); return 1.0f / (e0 + 1.0f); }
    else           { float e1 = expf(d);  return e1 / (1.0f + e1);  }
#endif
}

// Order-preserving bit flip: float compare == unsigned compare after flip.
__device__ __forceinline__ unsigned fflip(float f) {
    unsigned u = __float_as_uint(f);
    return u ^ (((unsigned)((int)u >> 31)) | 0x80000000u);
}

// ---------------------------------------------------------------------------
// Log-parallel cut over a 4096-bin smem histogram with 256 threads.
// *s_cut = flipped-bits threshold with count(>= thr) >= KK (0 if total < KK).
// Caller zeroes *s_cut + syncs before; syncs after.
// ---------------------------------------------------------------------------
__device__ __forceinline__ void cut_scan256(const int* __restrict__ hist,
                                            int* __restrict__ s_wtot,
                                            unsigned* __restrict__ s_cut,
                                            int t) {
    const int lane = t & 31;
    const int w    = t >> 5;
    const int seg  = 255 - t;                // descending bin order
    int val = 0;
    const int4* h4 = (const int4*)(hist + seg * 16);
    #pragma unroll
    for (int j = 0; j < 4; j++) { int4 a = h4[j]; val += a.x + a.y + a.z + a.w; }

    int incl = val;
    #pragma unroll
    for (int sh = 1; sh < 32; sh <<= 1) {
        int n = __shfl_up_sync(0xffffffffu, incl, sh);
        if (lane >= sh) incl += n;
    }
    if (lane == 31) s_wtot[w] = incl;
    __syncthreads();
    if (t < 8) {
        int v = s_wtot[t];
        int inc = v;
        #pragma unroll
        for (int sh = 1; sh < 8; sh <<= 1) {
            int n = __shfl_up_sync(0x000000ffu, inc, sh);
            if (t >= sh) inc += n;
        }
        s_wtot[t] = inc - v;                 // exclusive warp offset
    }
    __syncthreads();
    int excl = incl - val + s_wtot[w];       // count strictly above seg
    if (excl < KK && excl + val >= KK) {     // unique boundary thread
        int above = excl;
        int cut = seg * 16;
        #pragma unroll
        for (int c = seg * 16 + 15; c >= seg * 16; c--) {
            int hv = hist[c];
            if (above + hv >= KK) { cut = c; break; }
            above += hv;
        }
        *s_cut = ((unsigned)cut) << 20;
    }
}

// ---------------------------------------------------------------------------
// d-row loader: 4 adjacent cols; OOB (SAME padding) = -inf. col0 is 16B-aligned.
// ---------------------------------------------------------------------------
__device__ __forceinline__ float4 load_d4(const float* __restrict__ p0,
                                          const float* __restrict__ p1,
                                          int r, int c0, bool colok) {
    if (colok && ((unsigned)r < (unsigned)HH)) {
        float4 a = __ldg(reinterpret_cast<const float4*>(p0 + (size_t)r * WW + c0));
        float4 b = __ldg(reinterpret_cast<const float4*>(p1 + (size_t)r * WW + c0));
        return make_float4(b.x - a.x, b.y - a.y, b.z - a.z, b.w - a.w);
    }
    return make_float4(-INFINITY, -INFINITY, -INFINITY, -INFINITY);
}

// Horizontal 3-max for 4 cols; needs left/right neighbor edge values (2 shfl).
#define H3MAX4(D, HM) {                                          \
    float _dl = __shfl_up_sync(0xffffffffu, (D).w, 1);           \
    float _dr = __shfl_down_sync(0xffffffffu, (D).x, 1);         \
    (HM).x = fmaxf(_dl,   fmaxf((D).x, (D).y));                  \
    (HM).y = fmaxf((D).x, fmaxf((D).y, (D).z));                  \
    (HM).z = fmaxf((D).y, fmaxf((D).z, (D).w));                  \
    (HM).w = fmaxf((D).z, fmaxf((D).w, _dr)); }

// ---------------------------------------------------------------------------
// Fused kernel. Grid (1, 36, 16), block 256 (8 warps x 120 output cols each).
// ---------------------------------------------------------------------------
__global__ __launch_bounds__(NT) void fused_kernel(const float* __restrict__ in,
                                                   float* __restrict__ out) {
    __shared__ __align__(16) int  shist[HB];   // 16 KB
    __shared__ float2 s_q[QC];                  // 16 KB; overlaid by s_d/s_i
    __shared__ int    s_wtot[8];
    __shared__ unsigned s_cut;
    __shared__ int    s_qcnt, s_keep, s_gbase, s_sel;
    __shared__ int    s_n[NBY];

    const int b    = blockIdx.z;
    const int by   = blockIdx.y;
    const int tid  = threadIdx.x;
    const int w    = tid >> 5;
    const int lane = tid & 31;

    const int  c0    = w * 120 - 4 + 4 * lane;      // lane's first column
    const bool colok = ((unsigned)c0 < (unsigned)WW); // 4-col group fully in/out
    const int  r0    = by * RPB;

    #pragma unroll
    for (int i = tid; i < HB; i += NT) shist[i] = 0;
    if (tid == 0) { s_qcnt = 0; s_keep = 0; s_cut = 0u; }
    __syncthreads();

    const float* __restrict__ p0 = in + (size_t)b * 2 * HWSZ;
    const float* __restrict__ p1 = p0 + HWSZ;
    int*    __restrict__ gctr = &g_cnt[b][by];
    float2* __restrict__ gseg = g_cand[b][by];

    // Rolling vertical window of horizontal maxima.
    float4 d0, hmm, hm0;
    { float4 dm = load_d4(p0, p1, r0 - 1, c0, colok); H3MAX4(dm, hmm); }
    d0 = load_d4(p0, p1, r0, c0, colok);  H3MAX4(d0, hm0);

    const bool laneok = (lane >= 1) && (lane <= 30);

    #pragma unroll 5
    for (int r = r0; r < r0 + RPB; r++) {
        float4 dp = load_d4(p0, p1, r + 1, c0, colok);
        float4 hmp; H3MAX4(dp, hmp);

        float m0 = fmaxf(hmm.x, fmaxf(hm0.x, hmp.x));
        float m1 = fmaxf(hmm.y, fmaxf(hm0.y, hmp.y));
        float m2 = fmaxf(hmm.z, fmaxf(hm0.z, hmp.z));
        float m3 = fmaxf(hmm.w, fmaxf(hm0.w, hmp.w));

        bool k0 = laneok && (d0.x >= m0);
        bool k1 = laneok && (d0.y >= m1);
        bool k2 = laneok && (d0.z >= m2);
        bool k3 = laneok && (d0.w >= m3);

        if (k0 | k1 | k2 | k3) {                    // rare (~0.7% of pixels)
            const int ibase = r * WW + c0;
            #define EMIT(KB, DV, OFF)                                          \
                if (KB) {                                                      \
                    atomicAdd(&shist[fflip(DV) >> 20], 1);                     \
                    int _p = atomicAdd(&s_qcnt, 1);                            \
                    float2 _v = make_float2(DV, __int_as_float(ibase + OFF));  \
                    if (_p < QC) s_q[_p] = _v;                                 \
                    else { int _g = atomicAdd(gctr, 1);                        \
                           if (_g < SEGC) gseg[_g] = _v; }                     \
                }
            EMIT(k0, d0.x, 0)
            EMIT(k1, d0.y, 1)
            EMIT(k2, d0.z, 2)
            EMIT(k3, d0.w, 3)
            #undef EMIT
        }
        hmm = hm0; hm0 = hmp; d0 = dp;
    }

    // ---- Block-local top-100 cut, then filtered flush of the smem queue ----
    __syncthreads();
    cut_scan256(shist, s_wtot, &s_cut, tid);
    __syncthreads();
    const unsigned bcut = s_cut;
    const int qn = min(s_qcnt, QC);

    int cnt = 0;
    for (int i = tid; i < qn; i += NT)
        cnt += (fflip(s_q[i].x) >= bcut);
    if (cnt) atomicAdd(&s_keep, cnt);
    __syncthreads();
    if (tid == 0) {
        s_gbase = (s_keep > 0) ? atomicAdd(gctr, s_keep) : 0;
        s_keep = 0;
    }
    __syncthreads();
    for (int i = tid; i < qn; i += NT) {
        float2 v = s_q[i];
        if (fflip(v.x) >= bcut) {
            int p = s_gbase + atomicAdd(&s_keep, 1);
            if (p < SEGC) gseg[p] = v;
        }
    }

    // =====================================================================
    // "Last block done": last arriving block of this batch becomes selector.
    // =====================================================================
    __threadfence();                 // release candidate writes
    __syncthreads();
    if (tid == 0)
        s_sel = (atomicAdd(&g_done[b], 1) == NBY - 1) ? 1 : 0;
    __syncthreads();
    if (!s_sel) return;
    __threadfence();                 // acquire side

    // ---- Selector: re-init smem ----
    #pragma unroll
    for (int i = tid; i < HB; i += NT) shist[i] = 0;
    if (tid < NBY) s_n[tid] = min(g_cnt[b][tid], SEGC);
    if (tid == 0) { s_cut = 0u; s_keep = 0; }
    __syncthreads();

    if (tid < NBY) g_cnt[b][tid] = 0;       // reset for next graph replay
    if (tid == 0)  g_done[b] = 0;

    // Pass 1: histogram of the filtered candidates (~3.6k, L2-hot).
    for (int ch = 0; ch < NBY; ch++) {
        const int n = s_n[ch];
        const float2* __restrict__ cd = g_cand[b][ch];
        for (int i = tid; i < n; i += NT)
            atomicAdd(&shist[fflip(cd[i].x) >> 20], 1);
    }
    __syncthreads();

    cut_scan256(shist, s_wtot, &s_cut, tid);
    __syncthreads();
    const unsigned cutbits = s_cut;

    // Pass 2: collect survivors (>= cut) into the queue overlay.
    float* s_d = (float*)s_q;                // first 8 KB
    int*   s_i = (int*)(s_q + QC / 2);       // second 8 KB
    for (int ch = 0; ch < NBY; ch++) {
        const int n = s_n[ch];
        const float2* __restrict__ cd = g_cand[b][ch];
        for (int i = tid; i < n; i += NT) {
            float2 v = cd[i];
            if (fflip(v.x) >= cutbits) {
                int pos = atomicAdd(&s_keep, 1);
                if (pos < CAP) { s_d[pos] = v.x; s_i[pos] = __float_as_int(v.y); }
            }
        }
    }
    __syncthreads();

    const int C = min(s_keep, CAP);

    // Exact p in place, then exact stable rank: p desc, idx asc.
    for (int e = tid; e < C; e += NT) s_d[e] = prob_from_d(s_d[e]);
    __syncthreads();

    for (int e = tid; e < C; e += NT) {
        const float v  = s_d[e];
        const int   id = s_i[e];
        int rank = 0;
        for (int j = 0; j < C; j++) {
            float vj = s_d[j];
            rank += (vj > v) || (vj == v && s_i[j] < id);
        }
        if (rank < KK) {
            int ww = id % WW;
            int hh = id / WW;
            float xc = (float)ww * 4.0f + 1.5f;
            float yc = (float)hh * 4.0f + 1.5f;
            float* o = out + ((size_t)b * KK + rank) * 5;
            o[0] = xc - 10.0f;
            o[1] = yc - 10.0f;
            o[2] = xc + 10.0f;
            o[3] = yc + 10.0f;
            o[4] = v;
        }
    }
}

// ---------------------------------------------------------------------------
extern "C" void kernel_launch(void* const* d_in, const int* in_sizes, int n_in,
                              void* d_out, int out_size) {
    const float* in = (const float*)d_in[0];
    float* out = (float*)d_out;

    dim3 grid(1, NBY, BB);                        // (1, 36, 16) = 576 blocks
    fused_kernel<<<grid, NT>>>(in, out);
}

// round 10
// speedup vs baseline: 1.4524x; 1.4524x over previous
#include <cuda_runtime.h>
#include <math.h>
#include <stdint.h>

// FootAndBall ball-detection post-process — two kernels.
//  in : [16, 2, 540, 960] fp32 logits
//  out: [16, 100, 5] fp32 (x1,y1,x2,y2,score), score desc (idx asc on ties).
//
//  K1 detect : d = x1-x0 (NMS on d == NMS on softmax prob, monotone).
//    Software-pipelined float4 streaming NMS: rows processed in groups of 4
//    with double-buffered raw loads (8-20 independent LDG.128 in flight per
//    thread) to drive DRAM at bandwidth instead of MLP~2 latency (R8/R9 were
//    stuck at 740GB/s). Candidates (~11% of pixels) -> block smem queue +
//    smem histogram; block-local top-100 cut filters to ~100/block before ONE
//    contiguous per-batch global flush. Global top-100 of a batch is a subset
//    of the union of block-local top-100s; queue overflow falls back to
//    direct unfiltered global append (superset -> still correct).
//  K2 select : per-batch histogram of the ~5k contiguous filtered candidates,
//    cut, collect, exact (p desc, idx asc) rank, box write, counter reset.
//  __device__ globals start zero-initialized; K2 restores zeros.

#define BB   16
#define HH   540
#define WW   960
#define HWSZ (HH * WW)
#define KK   100

#define NT    256                 // detect threads per block (8 warps)
#define RPB   12                  // rows per block; 540 = 45 * 12
#define NBY   45                  // blocks per batch
#define QC    2048                // block smem queue entries (16 KB)
#define HB    4096                // histogram bins (top 12 flipped bits)
#define CAP   2048                // select survivor capacity (expected ~150)
#define CAPG  65536               // per-batch global candidate capacity

__device__ int    g_cnt [BB];
__device__ float2 g_cand[BB][CAPG];

// ---------------------------------------------------------------------------
// Exact softmax channel-1 prob from d = fl(x1-x0). Matches jax.nn.softmax:
// one exp arg is exactly 0 and fl(x0-x1) == -d exactly. (rel_err ~1e-12.)
// ---------------------------------------------------------------------------
__device__ __forceinline__ float prob_from_d(float d) {
#ifdef __FAST_MATH__
    double dd = (double)d;
    double p = (d >= 0.0f) ? (1.0 / (exp(-dd) + 1.0))
                           : (exp(dd) / (exp(dd) + 1.0));
    return (float)p;
#else
    if (d >= 0.0f) { float e0 = expf(-d); return 1.0f / (e0 + 1.0f); }
    else           { float e1 = expf(d);  return e1 / (1.0f + e1);  }
#endif
}

// Order-preserving bit flip: float compare == unsigned compare after flip.
__device__ __forceinline__ unsigned fflip(float f) {
    unsigned u = __float_as_uint(f);
    return u ^ (((unsigned)((int)u >> 31)) | 0x80000000u);
}

// ---------------------------------------------------------------------------
// Log-parallel cut over a 4096-bin smem histogram, 256-thread version.
// *s_cut = flipped-bits threshold with count(>= thr) >= KK (0 if total < KK).
// ---------------------------------------------------------------------------
__device__ __forceinline__ void cut_scan256(const int* __restrict__ hist,
                                            int* __restrict__ s_wtot,
                                            unsigned* __restrict__ s_cut,
                                            int t) {
    const int lane = t & 31;
    const int w    = t >> 5;
    const int seg  = 255 - t;                // descending bin order
    int val = 0;
    const int4* h4 = (const int4*)(hist + seg * 16);
    #pragma unroll
    for (int j = 0; j < 4; j++) { int4 a = h4[j]; val += a.x + a.y + a.z + a.w; }

    int incl = val;
    #pragma unroll
    for (int sh = 1; sh < 32; sh <<= 1) {
        int n = __shfl_up_sync(0xffffffffu, incl, sh);
        if (lane >= sh) incl += n;
    }
    if (lane == 31) s_wtot[w] = incl;
    __syncthreads();
    if (t < 8) {
        int v = s_wtot[t];
        int inc = v;
        #pragma unroll
        for (int sh = 1; sh < 8; sh <<= 1) {
            int n = __shfl_up_sync(0x000000ffu, inc, sh);
            if (t >= sh) inc += n;
        }
        s_wtot[t] = inc - v;
    }
    __syncthreads();
    int excl = incl - val + s_wtot[w];       // count strictly above seg
    if (excl < KK && excl + val >= KK) {     // unique boundary thread
        int above = excl;
        int cut = seg * 16;
        #pragma unroll
        for (int c = seg * 16 + 15; c >= seg * 16; c--) {
            int hv = hist[c];
            if (above + hv >= KK) { cut = c; break; }
            above += hv;
        }
        *s_cut = ((unsigned)cut) << 20;
    }
}

// 512-thread version (8 bins per thread) for the select kernel.
__device__ __forceinline__ void cut_scan512(const int* __restrict__ hist,
                                            int* __restrict__ s_wtot,
                                            unsigned* __restrict__ s_cut,
                                            int t) {
    const int lane = t & 31;
    const int w    = t >> 5;
    const int seg  = 511 - t;
    int val = 0;
    const int4* h4 = (const int4*)(hist + seg * 8);
    #pragma unroll
    for (int j = 0; j < 2; j++) { int4 a = h4[j]; val += a.x + a.y + a.z + a.w; }

    int incl = val;
    #pragma unroll
    for (int sh = 1; sh < 32; sh <<= 1) {
        int n = __shfl_up_sync(0xffffffffu, incl, sh);
        if (lane >= sh) incl += n;
    }
    if (lane == 31) s_wtot[w] = incl;
    __syncthreads();
    if (t < 16) {
        int v = s_wtot[t];
        int inc = v;
        #pragma unroll
        for (int sh = 1; sh < 16; sh <<= 1) {
            int n = __shfl_up_sync(0x0000ffffu, inc, sh);
            if (t >= sh) inc += n;
        }
        s_wtot[t] = inc - v;
    }
    __syncthreads();
    int excl = incl - val + s_wtot[w];
    if (excl < KK && excl + val >= KK) {
        int above = excl;
        int cut = seg * 8;
        #pragma unroll
        for (int c = seg * 8 + 7; c >= seg * 8; c--) {
            int hv = hist[c];
            if (above + hv >= KK) { cut = c; break; }
            above += hv;
        }
        *s_cut = ((unsigned)cut) << 20;
    }
}

// ---------------------------------------------------------------------------
// K1: pipelined register-streaming NMS + block-filtered contiguous emit.
// Grid (1, 45, 16), block 256 (8 warps x 120 output cols, 12 rows).
// ---------------------------------------------------------------------------
__global__ __launch_bounds__(NT) void detect_kernel(const float* __restrict__ in) {
    __shared__ __align__(16) int shist[HB];  // 16 KB
    __shared__ float2 s_q[QC];               // 16 KB
    __shared__ int    s_wtot[8];
    __shared__ unsigned s_bcut;
    __shared__ int    s_qcnt, s_keep, s_gbase;

    const int b    = blockIdx.z;
    const int by   = blockIdx.y;
    const int tid  = threadIdx.x;
    const int w    = tid >> 5;
    const int lane = tid & 31;

    const int  c0     = w * 120 - 4 + 4 * lane;          // lane's first column
    const bool colok  = ((unsigned)c0 < (unsigned)WW);
    const int  cc     = colok ? c0 : 0;                  // clamped load column
    const bool laneok = (lane >= 1) && (lane <= 30);
    const int  r0     = by * RPB;

    #pragma unroll
    for (int i = tid; i < HB; i += NT) shist[i] = 0;
    if (tid == 0) { s_qcnt = 0; s_keep = 0; s_bcut = 0u; }
    __syncthreads();

    const float* __restrict__ p0 = in + (size_t)b * 2 * HWSZ;
    const float* __restrict__ p1 = p0 + HWSZ;
    int*    __restrict__ gctr = &g_cnt[b];
    float2* __restrict__ gcd  = g_cand[b];

    // Unconditional clamped loads (always valid memory); validity applied at
    // conversion time. Keeps loads unpredicated -> free pipelining.
    #define LDROW(R, A, Bv) {                                                  \
        int _rr = (R) < 0 ? 0 : ((R) >= HH ? HH - 1 : (R));                    \
        size_t _o = (size_t)_rr * WW + cc;                                     \
        A  = __ldg(reinterpret_cast<const float4*>(p0 + _o));                  \
        Bv = __ldg(reinterpret_cast<const float4*>(p1 + _o)); }

    #define CVT(A, Bv, R, D) {                                                 \
        if (colok && ((unsigned)(R) < (unsigned)HH))                            \
            D = make_float4(Bv.x - A.x, Bv.y - A.y, Bv.z - A.z, Bv.w - A.w);    \
        else                                                                    \
            D = make_float4(-INFINITY, -INFINITY, -INFINITY, -INFINITY); }

    #define H3MAX4(D, HM) {                                                    \
        float _dl = __shfl_up_sync(0xffffffffu, (D).w, 1);                      \
        float _dr = __shfl_down_sync(0xffffffffu, (D).x, 1);                    \
        (HM).x = fmaxf(_dl,   fmaxf((D).x, (D).y));                             \
        (HM).y = fmaxf((D).x, fmaxf((D).y, (D).z));                             \
        (HM).z = fmaxf((D).y, fmaxf((D).z, (D).w));                             \
        (HM).w = fmaxf((D).z, fmaxf((D).w, _dr)); }

    #define EMIT1(K, V, IDX)                                                   \
        if (K) {                                                               \
            atomicAdd(&shist[fflip(V) >> 20], 1);                              \
            int _p = atomicAdd(&s_qcnt, 1);                                    \
            float2 _v = make_float2(V, __int_as_float(IDX));                   \
            if (_p < QC) s_q[_p] = _v;                                         \
            else { int _g = atomicAdd(gctr, 1);                                \
                   if (_g < CAPG) gcd[_g] = _v; }                              \
        }

    #define EMITROW(DC, HA, HBv, HC, R) {                                      \
        float _m0 = fmaxf((HA).x, fmaxf((HBv).x, (HC).x));                     \
        float _m1 = fmaxf((HA).y, fmaxf((HBv).y, (HC).y));                     \
        float _m2 = fmaxf((HA).z, fmaxf((HBv).z, (HC).z));                     \
        float _m3 = fmaxf((HA).w, fmaxf((HBv).w, (HC).w));                     \
        bool _k0 = laneok && ((DC).x >= _m0);                                  \
        bool _k1 = laneok && ((DC).y >= _m1);                                  \
        bool _k2 = laneok && ((DC).z >= _m2);                                  \
        bool _k3 = laneok && ((DC).w >= _m3);                                  \
        if (_k0 | _k1 | _k2 | _k3) {                                           \
            int _ib = (R) * WW + c0;                                           \
            EMIT1(_k0, (DC).x, _ib)                                            \
            EMIT1(_k1, (DC).y, _ib + 1)                                        \
            EMIT1(_k2, (DC).z, _ib + 2)                                        \
            EMIT1(_k3, (DC).w, _ib + 3)                                        \
        } }

    #define LOAD_GROUP(P, BASE)                                                \
        LDROW((BASE) + 1, P##1a, P##1b)                                        \
        LDROW((BASE) + 2, P##2a, P##2b)                                        \
        LDROW((BASE) + 3, P##3a, P##3b)                                        \
        LDROW((BASE) + 4, P##4a, P##4b)

    #define COMPUTE_GROUP(P, BASE) {                                           \
        float4 _d1, _d2, _d3, _d4, _h1, _h2, _h3, _h4;                         \
        CVT(P##1a, P##1b, (BASE) + 1, _d1)  H3MAX4(_d1, _h1)                   \
        CVT(P##2a, P##2b, (BASE) + 2, _d2)  H3MAX4(_d2, _h2)                   \
        CVT(P##3a, P##3b, (BASE) + 3, _d3)  H3MAX4(_d3, _h3)                   \
        CVT(P##4a, P##4b, (BASE) + 4, _d4)  H3MAX4(_d4, _h4)                   \
        EMITROW(dB, hmA, hmB, _h1, (BASE))                                     \
        EMITROW(_d1, hmB, _h1, _h2, (BASE) + 1)                                \
        EMITROW(_d2, _h1, _h2, _h3, (BASE) + 2)                                \
        EMITROW(_d3, _h2, _h3, _h4, (BASE) + 3)                                \
        hmA = _h3; hmB = _h4; dB = _d4; }

    // --- Prolog: rows r0-1, r0 (window) + preload first two groups ---------
    float4 A1a, A1b, A2a, A2b, A3a, A3b, A4a, A4b;
    float4 B1a, B1b, B2a, B2b, B3a, B3b, B4a, B4b;
    float4 hmA, hmB, dB;
    {
        float4 xa, xb, dm;
        LDROW(r0 - 1, xa, xb)
        LOAD_GROUP(A, r0)                    // rows r0+1..r0+4 (early)
        float4 ya, yb;
        LDROW(r0, ya, yb)
        LOAD_GROUP(B, r0 + 4)                // rows r0+5..r0+8 (early)
        CVT(xa, xb, r0 - 1, dm)  H3MAX4(dm, hmA)
        CVT(ya, yb, r0, dB)      H3MAX4(dB, hmB)
    }

    // --- Pipelined groups: 12 rows = 3 groups of 4 -------------------------
    COMPUTE_GROUP(A, r0)                     // rows r0..r0+3
    LOAD_GROUP(A, r0 + 8)                    // rows r0+9..r0+12 (early)
    COMPUTE_GROUP(B, r0 + 4)                 // rows r0+4..r0+7
    COMPUTE_GROUP(A, r0 + 8)                 // rows r0+8..r0+11

    // --- Block-local top-100 cut + filtered contiguous flush ---------------
    __syncthreads();
    cut_scan256(shist, s_wtot, &s_bcut, tid);
    __syncthreads();
    const unsigned bcut = s_bcut;
    const int qn = min(s_qcnt, QC);

    int cnt = 0;
    for (int i = tid; i < qn; i += NT)
        cnt += (fflip(s_q[i].x) >= bcut);
    if (cnt) atomicAdd(&s_keep, cnt);
    __syncthreads();
    if (tid == 0) {
        s_gbase = (s_keep > 0) ? atomicAdd(gctr, s_keep) : 0;
        s_keep = 0;
    }
    __syncthreads();
    for (int i = tid; i < qn; i += NT) {
        float2 v = s_q[i];
        if (fflip(v.x) >= bcut) {
            int p = s_gbase + atomicAdd(&s_keep, 1);
            if (p < CAPG) gcd[p] = v;
        }
    }
}

// ---------------------------------------------------------------------------
// K2: per-batch top-100 from ONE contiguous candidate array (~5k entries).
// Grid BB, block 512. Both passes are independent pipelined loads.
// ---------------------------------------------------------------------------
__global__ __launch_bounds__(512) void select_kernel(float* __restrict__ out) {
    __shared__ __align__(16) int shist[HB];  // 16 KB
    __shared__ int      s_wtot[16];
    __shared__ unsigned s_cut;
    __shared__ int      s_count;
    __shared__ float    s_d[CAP];            // 8 KB (d, overwritten by p)
    __shared__ int      s_i[CAP];            // 8 KB

    const int b = blockIdx.x;
    const int t = threadIdx.x;

    #pragma unroll
    for (int i = t; i < HB; i += 512) shist[i] = 0;
    if (t == 0) { s_cut = 0u; s_count = 0; }
    __syncthreads();

    const int n = min(g_cnt[b], CAPG);
    if (t == 0) g_cnt[b] = 0;               // reset for next graph replay
    const float2* __restrict__ cd = g_cand[b];

    // Pass 1: histogram (independent loads, pipelines fully).
    for (int i = t; i < n; i += 512)
        atomicAdd(&shist[fflip(cd[i].x) >> 20], 1);
    __syncthreads();

    cut_scan512(shist, s_wtot, &s_cut, t);
    __syncthreads();
    const unsigned cutbits = s_cut;

    // Pass 2: collect survivors (>= cut), now L1/L2-hot.
    for (int i = t; i < n; i += 512) {
        float2 v = cd[i];
        if (fflip(v.x) >= cutbits) {
            int pos = atomicAdd(&s_count, 1);
            if (pos < CAP) { s_d[pos] = v.x; s_i[pos] = __float_as_int(v.y); }
        }
    }
    __syncthreads();

    const int C = min(s_count, CAP);

    // Exact p in place, then exact stable rank: p desc, idx asc.
    for (int e = t; e < C; e += 512) s_d[e] = prob_from_d(s_d[e]);
    __syncthreads();

    for (int e = t; e < C; e += 512) {
        const float v  = s_d[e];
        const int   id = s_i[e];
        int rank = 0;
        for (int j = 0; j < C; j++) {
            float vj = s_d[j];
            rank += (vj > v) || (vj == v && s_i[j] < id);
        }
        if (rank < KK) {
            int ww = id % WW;
            int hh = id / WW;
            float xc = (float)ww * 4.0f + 1.5f;
            float yc = (float)hh * 4.0f + 1.5f;
            float* o = out + ((size_t)b * KK + rank) * 5;
            o[0] = xc - 10.0f;
            o[1] = yc - 10.0f;
            o[2] = xc + 10.0f;
            o[3] = yc + 10.0f;
            o[4] = v;
        }
    }
}

// ---------------------------------------------------------------------------
extern "C" void kernel_launch(void* const* d_in, const int* in_sizes, int n_in,
                              void* d_out, int out_size) {
    const float* in = (const float*)d_in[0];
    float* out = (float*)d_out;

    dim3 grid(1, NBY, BB);                    // (1, 45, 16) = 720 blocks
    detect_kernel<<<grid, NT>>>(in);

    select_kernel<<<BB, 512>>>(out);
}

// round 11
// speedup vs baseline: 1.4950x; 1.0293x over previous
#include <cuda_runtime.h>
#include <math.h>
#include <stdint.h>

// FootAndBall ball-detection post-process — two kernels.
//  in : [16, 2, 540, 960] fp32 logits
//  out: [16, 100, 5] fp32 (x1,y1,x2,y2,score), score desc (idx asc on ties).
//
//  K1 detect : d = x1-x0 (NMS on d == NMS on softmax prob, monotone).
//    Software-pipelined float4 streaming NMS (groups of 4 rows, double
//    buffered -> 8+ independent LDG.128 in flight). Candidates -> block smem
//    queue + smem histogram; block-local top-100 cut filters to ~100/block
//    before ONE contiguous per-batch flush. Global top-100 ⊆ union of
//    block-local top-100s; queue overflow falls back to direct unfiltered
//    global append (superset -> still correct).
//  K2 select : REGISTER-RESIDENT single-round select. Up to 16 candidates
//    per thread loaded in one fully-unrolled unpredicated burst (1 memory
//    round trip instead of 9); histogram + cut from registers; collect from
//    registers (no second pass); exact (p desc, idx asc) rank; box write;
//    counter reset. Overflow (>8192 cands, only via fallback path) handled
//    by a rare slow loop.
//  __device__ globals start zero-initialized; K2 restores zeros.

#define BB   16
#define HH   540
#define WW   960
#define HWSZ (HH * WW)
#define KK   100

#define NT    256                 // detect threads per block (8 warps)
#define RPB   12                  // rows per block; 540 = 45 * 12
#define NBY   45                  // blocks per batch
#define QC    2048                // block smem queue entries (16 KB)
#define HB    4096                // histogram bins (top 12 flipped bits)
#define CAP   2048                // select survivor capacity (expected ~150)
#define CAPG  65536               // per-batch global candidate capacity
#define RPT   16                  // select: candidates per thread (512*16=8192)

__device__ int    g_cnt [BB];
__device__ float2 g_cand[BB][CAPG];

// ---------------------------------------------------------------------------
// Exact softmax channel-1 prob from d = fl(x1-x0). Matches jax.nn.softmax:
// one exp arg is exactly 0 and fl(x0-x1) == -d exactly. (rel_err ~1e-12.)
// ---------------------------------------------------------------------------
__device__ __forceinline__ float prob_from_d(float d) {
#ifdef __FAST_MATH__
    double dd = (double)d;
    double p = (d >= 0.0f) ? (1.0 / (exp(-dd) + 1.0))
                           : (exp(dd) / (exp(dd) + 1.0));
    return (float)p;
#else
    if (d >= 0.0f) { float e0 = expf(-d); return 1.0f / (e0 + 1.0f); }
    else           { float e1 = expf(d);  return e1 / (1.0f + e1);  }
#endif
}

// Order-preserving bit flip: float compare == unsigned compare after flip.
__device__ __forceinline__ unsigned fflip(float f) {
    unsigned u = __float_as_uint(f);
    return u ^ (((unsigned)((int)u >> 31)) | 0x80000000u);
}

// ---------------------------------------------------------------------------
// Log-parallel cut over a 4096-bin smem histogram, 256-thread version.
// *s_cut = flipped-bits threshold with count(>= thr) >= KK (0 if total < KK).
// ---------------------------------------------------------------------------
__device__ __forceinline__ void cut_scan256(const int* __restrict__ hist,
                                            int* __restrict__ s_wtot,
                                            unsigned* __restrict__ s_cut,
                                            int t) {
    const int lane = t & 31;
    const int w    = t >> 5;
    const int seg  = 255 - t;                // descending bin order
    int val = 0;
    const int4* h4 = (const int4*)(hist + seg * 16);
    #pragma unroll
    for (int j = 0; j < 4; j++) { int4 a = h4[j]; val += a.x + a.y + a.z + a.w; }

    int incl = val;
    #pragma unroll
    for (int sh = 1; sh < 32; sh <<= 1) {
        int n = __shfl_up_sync(0xffffffffu, incl, sh);
        if (lane >= sh) incl += n;
    }
    if (lane == 31) s_wtot[w] = incl;
    __syncthreads();
    if (t < 8) {
        int v = s_wtot[t];
        int inc = v;
        #pragma unroll
        for (int sh = 1; sh < 8; sh <<= 1) {
            int n = __shfl_up_sync(0x000000ffu, inc, sh);
            if (t >= sh) inc += n;
        }
        s_wtot[t] = inc - v;
    }
    __syncthreads();
    int excl = incl - val + s_wtot[w];       // count strictly above seg
    if (excl < KK && excl + val >= KK) {     // unique boundary thread
        int above = excl;
        int cut = seg * 16;
        #pragma unroll
        for (int c = seg * 16 + 15; c >= seg * 16; c--) {
            int hv = hist[c];
            if (above + hv >= KK) { cut = c; break; }
            above += hv;
        }
        *s_cut = ((unsigned)cut) << 20;
    }
}

// 512-thread version (8 bins per thread) for the select kernel.
__device__ __forceinline__ void cut_scan512(const int* __restrict__ hist,
                                            int* __restrict__ s_wtot,
                                            unsigned* __restrict__ s_cut,
                                            int t) {
    const int lane = t & 31;
    const int w    = t >> 5;
    const int seg  = 511 - t;
    int val = 0;
    const int4* h4 = (const int4*)(hist + seg * 8);
    #pragma unroll
    for (int j = 0; j < 2; j++) { int4 a = h4[j]; val += a.x + a.y + a.z + a.w; }

    int incl = val;
    #pragma unroll
    for (int sh = 1; sh < 32; sh <<= 1) {
        int n = __shfl_up_sync(0xffffffffu, incl, sh);
        if (lane >= sh) incl += n;
    }
    if (lane == 31) s_wtot[w] = incl;
    __syncthreads();
    if (t < 16) {
        int v = s_wtot[t];
        int inc = v;
        #pragma unroll
        for (int sh = 1; sh < 16; sh <<= 1) {
            int n = __shfl_up_sync(0x0000ffffu, inc, sh);
            if (t >= sh) inc += n;
        }
        s_wtot[t] = inc - v;
    }
    __syncthreads();
    int excl = incl - val + s_wtot[w];
    if (excl < KK && excl + val >= KK) {
        int above = excl;
        int cut = seg * 8;
        #pragma unroll
        for (int c = seg * 8 + 7; c >= seg * 8; c--) {
            int hv = hist[c];
            if (above + hv >= KK) { cut = c; break; }
            above += hv;
        }
        *s_cut = ((unsigned)cut) << 20;
    }
}

// ---------------------------------------------------------------------------
// K1: pipelined register-streaming NMS + block-filtered contiguous emit.
// Grid (1, 45, 16), block 256 (8 warps x 120 output cols, 12 rows).
// (Unchanged from R10 — best detect measured so far.)
// ---------------------------------------------------------------------------
__global__ __launch_bounds__(NT) void detect_kernel(const float* __restrict__ in) {
    __shared__ __align__(16) int shist[HB];  // 16 KB
    __shared__ float2 s_q[QC];               // 16 KB
    __shared__ int    s_wtot[8];
    __shared__ unsigned s_bcut;
    __shared__ int    s_qcnt, s_keep, s_gbase;

    const int b    = blockIdx.z;
    const int by   = blockIdx.y;
    const int tid  = threadIdx.x;
    const int w    = tid >> 5;
    const int lane = tid & 31;

    const int  c0     = w * 120 - 4 + 4 * lane;          // lane's first column
    const bool colok  = ((unsigned)c0 < (unsigned)WW);
    const int  cc     = colok ? c0 : 0;                  // clamped load column
    const bool laneok = (lane >= 1) && (lane <= 30);
    const int  r0     = by * RPB;

    #pragma unroll
    for (int i = tid; i < HB; i += NT) shist[i] = 0;
    if (tid == 0) { s_qcnt = 0; s_keep = 0; s_bcut = 0u; }
    __syncthreads();

    const float* __restrict__ p0 = in + (size_t)b * 2 * HWSZ;
    const float* __restrict__ p1 = p0 + HWSZ;
    int*    __restrict__ gctr = &g_cnt[b];
    float2* __restrict__ gcd  = g_cand[b];

    #define LDROW(R, A, Bv) {                                                  \
        int _rr = (R) < 0 ? 0 : ((R) >= HH ? HH - 1 : (R));                    \
        size_t _o = (size_t)_rr * WW + cc;                                     \
        A  = __ldg(reinterpret_cast<const float4*>(p0 + _o));                  \
        Bv = __ldg(reinterpret_cast<const float4*>(p1 + _o)); }

    #define CVT(A, Bv, R, D) {                                                 \
        if (colok && ((unsigned)(R) < (unsigned)HH))                            \
            D = make_float4(Bv.x - A.x, Bv.y - A.y, Bv.z - A.z, Bv.w - A.w);    \
        else                                                                    \
            D = make_float4(-INFINITY, -INFINITY, -INFINITY, -INFINITY); }

    #define H3MAX4(D, HM) {                                                    \
        float _dl = __shfl_up_sync(0xffffffffu, (D).w, 1);                      \
        float _dr = __shfl_down_sync(0xffffffffu, (D).x, 1);                    \
        (HM).x = fmaxf(_dl,   fmaxf((D).x, (D).y));                             \
        (HM).y = fmaxf((D).x, fmaxf((D).y, (D).z));                             \
        (HM).z = fmaxf((D).y, fmaxf((D).z, (D).w));                             \
        (HM).w = fmaxf((D).z, fmaxf((D).w, _dr)); }

    #define EMIT1(K, V, IDX)                                                   \
        if (K) {                                                               \
            atomicAdd(&shist[fflip(V) >> 20], 1);                              \
            int _p = atomicAdd(&s_qcnt, 1);                                    \
            float2 _v = make_float2(V, __int_as_float(IDX));                   \
            if (_p < QC) s_q[_p] = _v;                                         \
            else { int _g = atomicAdd(gctr, 1);                                \
                   if (_g < CAPG) gcd[_g] = _v; }                              \
        }

    #define EMITROW(DC, HA, HBv, HC, R) {                                      \
        float _m0 = fmaxf((HA).x, fmaxf((HBv).x, (HC).x));                     \
        float _m1 = fmaxf((HA).y, fmaxf((HBv).y, (HC).y));                     \
        float _m2 = fmaxf((HA).z, fmaxf((HBv).z, (HC).z));                     \
        float _m3 = fmaxf((HA).w, fmaxf((HBv).w, (HC).w));                     \
        bool _k0 = laneok && ((DC).x >= _m0);                                  \
        bool _k1 = laneok && ((DC).y >= _m1);                                  \
        bool _k2 = laneok && ((DC).z >= _m2);                                  \
        bool _k3 = laneok && ((DC).w >= _m3);                                  \
        if (_k0 | _k1 | _k2 | _k3) {                                           \
            int _ib = (R) * WW + c0;                                           \
            EMIT1(_k0, (DC).x, _ib)                                            \
            EMIT1(_k1, (DC).y, _ib + 1)                                        \
            EMIT1(_k2, (DC).z, _ib + 2)                                        \
            EMIT1(_k3, (DC).w, _ib + 3)                                        \
        } }

    #define LOAD_GROUP(P, BASE)                                                \
        LDROW((BASE) + 1, P##1a, P##1b)                                        \
        LDROW((BASE) + 2, P##2a, P##2b)                                        \
        LDROW((BASE) + 3, P##3a, P##3b)                                        \
        LDROW((BASE) + 4, P##4a, P##4b)

    #define COMPUTE_GROUP(P, BASE) {                                           \
        float4 _d1, _d2, _d3, _d4, _h1, _h2, _h3, _h4;                         \
        CVT(P##1a, P##1b, (BASE) + 1, _d1)  H3MAX4(_d1, _h1)                   \
        CVT(P##2a, P##2b, (BASE) + 2, _d2)  H3MAX4(_d2, _h2)                   \
        CVT(P##3a, P##3b, (BASE) + 3, _d3)  H3MAX4(_d3, _h3)                   \
        CVT(P##4a, P##4b, (BASE) + 4, _d4)  H3MAX4(_d4, _h4)                   \
        EMITROW(dB, hmA, hmB, _h1, (BASE))                                     \
        EMITROW(_d1, hmB, _h1, _h2, (BASE) + 1)                                \
        EMITROW(_d2, _h1, _h2, _h3, (BASE) + 2)                                \
        EMITROW(_d3, _h2, _h3, _h4, (BASE) + 3)                                \
        hmA = _h3; hmB = _h4; dB = _d4; }

    float4 A1a, A1b, A2a, A2b, A3a, A3b, A4a, A4b;
    float4 B1a, B1b, B2a, B2b, B3a, B3b, B4a, B4b;
    float4 hmA, hmB, dB;
    {
        float4 xa, xb, dm;
        LDROW(r0 - 1, xa, xb)
        LOAD_GROUP(A, r0)                    // rows r0+1..r0+4 (early)
        float4 ya, yb;
        LDROW(r0, ya, yb)
        LOAD_GROUP(B, r0 + 4)                // rows r0+5..r0+8 (early)
        CVT(xa, xb, r0 - 1, dm)  H3MAX4(dm, hmA)
        CVT(ya, yb, r0, dB)      H3MAX4(dB, hmB)
    }

    COMPUTE_GROUP(A, r0)                     // rows r0..r0+3
    LOAD_GROUP(A, r0 + 8)                    // rows r0+9..r0+12 (early)
    COMPUTE_GROUP(B, r0 + 4)                 // rows r0+4..r0+7
    COMPUTE_GROUP(A, r0 + 8)                 // rows r0+8..r0+11

    // --- Block-local top-100 cut + filtered contiguous flush ---------------
    __syncthreads();
    cut_scan256(shist, s_wtot, &s_bcut, tid);
    __syncthreads();
    const unsigned bcut = s_bcut;
    const int qn = min(s_qcnt, QC);

    int cnt = 0;
    for (int i = tid; i < qn; i += NT)
        cnt += (fflip(s_q[i].x) >= bcut);
    if (cnt) atomicAdd(&s_keep, cnt);
    __syncthreads();
    if (tid == 0) {
        s_gbase = (s_keep > 0) ? atomicAdd(gctr, s_keep) : 0;
        s_keep = 0;
    }
    __syncthreads();
    for (int i = tid; i < qn; i += NT) {
        float2 v = s_q[i];
        if (fflip(v.x) >= bcut) {
            int p = s_gbase + atomicAdd(&s_keep, 1);
            if (p < CAPG) gcd[p] = v;
        }
    }
}

// ---------------------------------------------------------------------------
// K2: register-resident per-batch top-100. Grid BB, block 512.
// One unrolled unpredicated load burst (RPT LDG.64 per thread, MLP=16);
// histogram + collect both from registers -> 1 memory round instead of 18.
// ---------------------------------------------------------------------------
__global__ __launch_bounds__(512) void select_kernel(float* __restrict__ out) {
    __shared__ __align__(16) int shist[HB];  // 16 KB
    __shared__ int      s_wtot[16];
    __shared__ unsigned s_cut;
    __shared__ int      s_count;
    __shared__ float    s_d[CAP];            // 8 KB (d, overwritten by p)
    __shared__ int      s_i[CAP];            // 8 KB

    const int b = blockIdx.x;
    const int t = threadIdx.x;

    {   // vectorized smem hist zero: 2x int4 per thread
        int4* h4 = (int4*)shist;
        h4[t]       = make_int4(0, 0, 0, 0);
        h4[t + 512] = make_int4(0, 0, 0, 0);
    }
    if (t == 0) { s_cut = 0u; s_count = 0; }

    const int n = min(g_cnt[b], CAPG);
    if (t == 0) g_cnt[b] = 0;               // reset for next graph replay
    const float2* __restrict__ cd = g_cand[b];

    // ---- One unpredicated load burst: all RPT loads issue back-to-back ----
    float2 v[RPT];
    #pragma unroll
    for (int j = 0; j < RPT; j++) {
        int idx = t + j * 512;
        int ii  = (idx < n) ? idx : 0;       // clamp keeps the load legal
        v[j] = __ldg(cd + ii);
    }
    __syncthreads();                          // hist zero complete

    // ---- Histogram from registers ----
    #pragma unroll
    for (int j = 0; j < RPT; j++)
        if (t + j * 512 < n)
            atomicAdd(&shist[fflip(v[j].x) >> 20], 1);

    // Rare overflow (only via detect's unfiltered fallback path).
    for (int i = 512 * RPT + t; i < n; i += 512)
        atomicAdd(&shist[fflip(cd[i].x) >> 20], 1);
    __syncthreads();

    cut_scan512(shist, s_wtot, &s_cut, t);
    __syncthreads();
    const unsigned cutbits = s_cut;

    // ---- Collect survivors from registers (no second memory pass) ----
    #pragma unroll
    for (int j = 0; j < RPT; j++) {
        if (t + j * 512 < n && fflip(v[j].x) >= cutbits) {
            int pos = atomicAdd(&s_count, 1);
            if (pos < CAP) { s_d[pos] = v[j].x; s_i[pos] = __float_as_int(v[j].y); }
        }
    }
    for (int i = 512 * RPT + t; i < n; i += 512) {   // rare overflow
        float2 vv = cd[i];
        if (fflip(vv.x) >= cutbits) {
            int pos = atomicAdd(&s_count, 1);
            if (pos < CAP) { s_d[pos] = vv.x; s_i[pos] = __float_as_int(vv.y); }
        }
    }
    __syncthreads();

    const int C = min(s_count, CAP);

    // ---- Exact p in place, then exact stable rank: p desc, idx asc ----
    for (int e = t; e < C; e += 512) s_d[e] = prob_from_d(s_d[e]);
    __syncthreads();

    for (int e = t; e < C; e += 512) {
        const float p  = s_d[e];
        const int   id = s_i[e];
        int rank = 0;
        for (int j = 0; j < C; j++) {
            float pj = s_d[j];
            rank += (pj > p) || (pj == p && s_i[j] < id);
        }
        if (rank < KK) {
            int ww = id % WW;
            int hh = id / WW;
            float xc = (float)ww * 4.0f + 1.5f;
            float yc = (float)hh * 4.0f + 1.5f;
            float* o = out + ((size_t)b * KK + rank) * 5;
            o[0] = xc - 10.0f;
            o[1] = yc - 10.0f;
            o[2] = xc + 10.0f;
            o[3] = yc + 10.0f;
            o[4] = p;
        }
    }
}

// ---------------------------------------------------------------------------
extern "C" void kernel_launch(void* const* d_in, const int* in_sizes, int n_in,
                              void* d_out, int out_size) {
    const float* in = (const float*)d_in[0];
    float* out = (float*)d_out;

    dim3 grid(1, NBY, BB);                    // (1, 45, 16) = 720 blocks
    detect_kernel<<<grid, NT>>>(in);

    select_kernel<<<BB, 512>>>(out);
}